// round 16
// baseline (speedup 1.0000x reference)
#include <cuda_runtime.h>
#include <cuda_fp16.h>
#include <math_constants.h>
#include <mma.h>

using namespace nvcuda;

#define N_MAX 50000
#define E_MAX 800000
#define F1 128
#define SLOPE 0.2f
#define FULL 0xffffffffu
#define SCAN_B 512

// ---------------- scratch ----------------
__device__ __half2 g_ft1h[N_MAX * 64];   // layer-1 features, fp16 pairs
__device__ float2 g_el1[N_MAX];
__device__ float2 g_er1[N_MAX];
__device__ __half g_ft2h[N_MAX * 16];    // layer-2 features (gathered), fp16
__device__ float g_res[N_MAX * 16];      // residual
__device__ float g_el2[N_MAX];
__device__ float g_er2[N_MAX];
__device__ float g_inv2[N_MAX];          // 1/sum for layer-2 softmax
__device__ float g_Wc[F1 * 32];          // [W2 | Wres]
__device__ __half g_W1h[F1 * F1];        // W1 in fp16 (k-major [k][n])
__device__ int g_deg[N_MAX];             // zeroed at load; re-zeroed by scan_add
__device__ int g_rowptr[N_MAX + 1];
__device__ int g_cursor[N_MAX];
__device__ int g_blocksum[128];
__device__ int g_pos[E_MAX];             // original edge i -> sorted slot
__device__ int2 g_exw1[E_MAX];           // sorted: (src, ex0|ex1 fp16x2)
__device__ int2 g_exw2[E_MAX];           // sorted: (src, ex fp32 bits)

__device__ __forceinline__ float lrelu(float x) { return x > 0.f ? x : SLOPE * x; }
__device__ __forceinline__ float eluf(float x)  { return x > 0.f ? x : __expf(x) - 1.f; }

// ---------------- side-stream pack: Wc + W1->fp16 ----------------
__global__ void pack_kernel(const float* __restrict__ W1,
                            const float* __restrict__ W2,
                            const float* __restrict__ Wres) {
    int i = blockIdx.x * blockDim.x + threadIdx.x;
    if (i < F1 * F1) g_W1h[i] = __float2half(W1[i]);
    if (i < F1 * 32) {
        int k = i >> 5, c = i & 31;
        g_Wc[i] = (c < 16) ? W2[k * 16 + c] : Wres[k * 16 + (c - 16)];
    }
}

// ---------------- CSR build ----------------
__global__ void deg_kernel(const int* __restrict__ dst, int e) {
    int base = (blockIdx.x * blockDim.x + threadIdx.x) * 4;
    if (base + 4 <= e) {
        int4 a = *(const int4*)(dst + base);
        atomicAdd(&g_deg[a.x], 1); atomicAdd(&g_deg[a.y], 1);
        atomicAdd(&g_deg[a.z], 1); atomicAdd(&g_deg[a.w], 1);
    } else {
        for (int k = base; k < e; k++) atomicAdd(&g_deg[dst[k]], 1);
    }
}

__global__ void scan_local(int n) {
    __shared__ int sm[SCAN_B];
    int t = threadIdx.x;
    int i = blockIdx.x * SCAN_B + t;
    int v = (i < n) ? g_deg[i] : 0;
    sm[t] = v;
    __syncthreads();
    for (int off = 1; off < SCAN_B; off <<= 1) {
        int u = (t >= off) ? sm[t - off] : 0;
        __syncthreads();
        sm[t] += u;
        __syncthreads();
    }
    if (i < n) g_rowptr[i] = sm[t] - v;
    if (t == SCAN_B - 1) g_blocksum[blockIdx.x] = sm[t];
}

__global__ void scan_add(int n, int e, int nb) {
    __shared__ int bs[128];
    int t = threadIdx.x;
    if (t < 128) bs[t] = (t < nb) ? g_blocksum[t] : 0;
    __syncthreads();
    for (int off = 1; off < 128; off <<= 1) {
        int u = 0;
        if (t < 128 && t >= off) u = bs[t - off];
        __syncthreads();
        if (t < 128) bs[t] += u;
        __syncthreads();
    }
    int i = blockIdx.x * blockDim.x + t;
    if (i < n) {
        int b = i / SCAN_B;
        int v = g_rowptr[i] + ((b == 0) ? 0 : bs[b - 1]);
        g_rowptr[i] = v;
        g_cursor[i] = v;
        g_deg[i] = 0;
    }
    if (i == n) g_rowptr[n] = e;
}

// scatter: only assigns sorted slots; g_pos write is COALESCED
__global__ void scatter_kernel(const int* __restrict__ dst, int e) {
    int base = (blockIdx.x * blockDim.x + threadIdx.x) * 2;
    if (base + 2 <= e) {
        int2 d = *(const int2*)(dst + base);
        int p0 = atomicAdd(&g_cursor[d.x], 1);
        int p1 = atomicAdd(&g_cursor[d.y], 1);
        *(int2*)(g_pos + base) = make_int2(p0, p1);
    } else {
        for (int k = base; k < e; k++)
            g_pos[k] = atomicAdd(&g_cursor[dst[k]], 1);
    }
}

// ---------------- GEMM1 via WMMA fp16 + fused el1/er1 ----------------
__global__ void gemm1_wmma(const float* __restrict__ h,
                           const float* __restrict__ al1,
                           const float* __restrict__ ar1, int n) {
    __shared__ __half a_sm[32][F1];
    __shared__ float c_sm[32][F1];
    int t = threadIdx.x;
    int warp = t >> 5, lane = t & 31;
    int row0 = blockIdx.x * 32;

    for (int i = t; i < 1024; i += 256) {
        int r = i >> 5, j4 = i & 31;
        int row = row0 + r;
        float4 v = make_float4(0.f, 0.f, 0.f, 0.f);
        if (row < n) v = *(const float4*)(h + row * F1 + j4 * 4);
        *(__half2*)&a_sm[r][j4 * 4]     = __floats2half2_rn(v.x, v.y);
        *(__half2*)&a_sm[r][j4 * 4 + 2] = __floats2half2_rn(v.z, v.w);
    }
    __syncthreads();

    wmma::fragment<wmma::accumulator, 16, 16, 16, float> c0, c1;
    wmma::fill_fragment(c0, 0.f);
    wmma::fill_fragment(c1, 0.f);
    int trow = (warp >> 2) * 16;
    int tcol = (warp & 3) * 32;
#pragma unroll
    for (int k = 0; k < F1; k += 16) {
        wmma::fragment<wmma::matrix_a, 16, 16, 16, __half, wmma::row_major> a;
        wmma::load_matrix_sync(a, &a_sm[trow][k], F1);
        wmma::fragment<wmma::matrix_b, 16, 16, 16, __half, wmma::row_major> b;
        wmma::load_matrix_sync(b, &g_W1h[k * F1 + tcol], F1);
        wmma::mma_sync(c0, a, b, c0);
        wmma::load_matrix_sync(b, &g_W1h[k * F1 + tcol + 16], F1);
        wmma::mma_sync(c1, a, b, c1);
    }
    wmma::store_matrix_sync(&c_sm[trow][tcol], c0, F1, wmma::mem_row_major);
    wmma::store_matrix_sync(&c_sm[trow][tcol + 16], c1, F1, wmma::mem_row_major);
    __syncthreads();

    for (int i = t; i < 32 * 64; i += 256) {
        int r = i >> 6, c2 = i & 63;
        int row = row0 + r;
        if (row < n)
            g_ft1h[row * 64 + c2] = __floats2half2_rn(c_sm[r][c2 * 2], c_sm[r][c2 * 2 + 1]);
    }
    float a0 = al1[lane], a1 = al1[lane + 32], a2 = al1[lane + 64], a3 = al1[lane + 96];
    float r0 = ar1[lane], r1 = ar1[lane + 32], r2 = ar1[lane + 64], r3 = ar1[lane + 96];
#pragma unroll
    for (int rr = 0; rr < 4; rr++) {
        int r = warp * 4 + rr;
        int row = row0 + r;
        float f0 = c_sm[r][lane], f1 = c_sm[r][lane + 32];
        float f2 = c_sm[r][lane + 64], f3 = c_sm[r][lane + 96];
        float el0 = f0 * a0 + f1 * a1, er0 = f0 * r0 + f1 * r1;
        float el1v = f2 * a2 + f3 * a3, er1v = f2 * r2 + f3 * r3;
#pragma unroll
        for (int o = 16; o; o >>= 1) {
            el0  += __shfl_xor_sync(FULL, el0, o);
            er0  += __shfl_xor_sync(FULL, er0, o);
            el1v += __shfl_xor_sync(FULL, el1v, o);
            er1v += __shfl_xor_sync(FULL, er1v, o);
        }
        if (lane == 0 && row < n) {
            g_el1[row] = make_float2(el0, el1v);
            g_er1[row] = make_float2(er0, er1v);
        }
    }
}

// ---- edge-parallel precompute of layer-1 ex (coalesced reads) ----
__global__ void exw1_kernel(const int* __restrict__ src,
                            const int* __restrict__ dst, int e) {
    int i = blockIdx.x * blockDim.x + threadIdx.x;
    if (i >= e) return;
    int s = src[i], d = dst[i];
    float2 el = g_el1[s];
    float2 er = g_er1[d];
    float ex0 = __expf(lrelu(el.x + er.x));
    float ex1 = __expf(lrelu(el.y + er.y));
    __half2 hp = __floats2half2_rn(ex0, ex1);
    g_exw1[g_pos[i]] = make_int2(s, *reinterpret_cast<int*>(&hp));
}

// ------ FUSED: layer-1 aggregation + GEMM2 + el2/er2 (NO shfl, NO exp) ------
__global__ void l2_fused_kernel(const float* __restrict__ b1,
                                const float* __restrict__ al2,
                                const float* __restrict__ ar2, int n) {
    __shared__ float hs[16][F1];
    int t = threadIdx.x;
    int lane = t & 31, w = t >> 5;
    int row0 = blockIdx.x * 16;

    float4 bv = *(const float4*)(b1 + lane * 4);

    // ---- phase A: aggregate 4 nodes per warp ----
#pragma unroll
    for (int rr = 0; rr < 4; rr++) {
        int r = w * 4 + rr;
        int node = row0 + r;
        if (node >= n) {
            *(float4*)&hs[r][lane * 4] = make_float4(0.f, 0.f, 0.f, 0.f);
            continue;
        }
        int beg = g_rowptr[node], end = g_rowptr[node + 1];
        float4 acc = make_float4(0.f, 0.f, 0.f, 0.f);
        float ssum = 0.f;   // every lane sees every edge -> no reduction needed
#pragma unroll 8
        for (int k = beg; k < end; k++) {
            int2 p = __ldg(&g_exw1[k]);           // uniform, sequential, L1-hot
            __half2 hx = *reinterpret_cast<__half2*>(&p.y);
            float x = (lane < 16) ? __low2float(hx) : __high2float(hx);
            ssum += x;
            uint2 raw = *(const uint2*)(g_ft1h + p.x * 64 + lane * 2);
            float2 f01 = __half22float2(*reinterpret_cast<__half2*>(&raw.x));
            float2 f23 = __half22float2(*reinterpret_cast<__half2*>(&raw.y));
            acc.x += x * f01.x;
            acc.y += x * f01.y;
            acc.z += x * f23.x;
            acc.w += x * f23.y;
        }
        float inv = (ssum > 0.f) ? 1.f / ssum : 0.f;
        float4 o4;
        o4.x = eluf(acc.x * inv + bv.x);
        o4.y = eluf(acc.y * inv + bv.y);
        o4.z = eluf(acc.z * inv + bv.z);
        o4.w = eluf(acc.w * inv + bv.w);
        *(float4*)&hs[r][lane * 4] = o4;
    }
    __syncthreads();

    // ---- phase B: gemm2 ([ft2 | res] = h1 @ [W2 | Wres]) + eler2 ----
    int c = t & 31, g = t >> 5;
    float acc2[4] = {0.f, 0.f, 0.f, 0.f};
    for (int k = 0; k < F1; k += 4) {
        float w0 = g_Wc[k * 32 + c];
        float w1 = g_Wc[(k + 1) * 32 + c];
        float w2 = g_Wc[(k + 2) * 32 + c];
        float w3 = g_Wc[(k + 3) * 32 + c];
#pragma unroll
        for (int rr = 0; rr < 4; rr++) {
            float4 hv = *(const float4*)&hs[g * 4 + rr][k];
            acc2[rr] += hv.x * w0 + hv.y * w1 + hv.z * w2 + hv.w * w3;
        }
    }
    float a2 = (c < 16) ? al2[c] : 0.f;
    float r2v = (c < 16) ? ar2[c] : 0.f;
#pragma unroll
    for (int rr = 0; rr < 4; rr++) {
        int row = row0 + g * 4 + rr;
        if (row < n) {
            if (c < 16) g_ft2h[row * 16 + c] = __float2half(acc2[rr]);
            else        g_res[row * 16 + (c - 16)] = acc2[rr];
        }
        float el = acc2[rr] * a2, er = acc2[rr] * r2v;
#pragma unroll
        for (int o = 8; o; o >>= 1) {
            el += __shfl_xor_sync(FULL, el, o);
            er += __shfl_xor_sync(FULL, er, o);
        }
        if (c == 0 && row < n) {
            g_el2[row] = el;
            g_er2[row] = er;
        }
    }
}

// ---- edge-parallel precompute of layer-2 ex (fp32, coalesced reads) ----
__global__ void exw2_kernel(const int* __restrict__ src,
                            const int* __restrict__ dst, int e) {
    int i = blockIdx.x * blockDim.x + threadIdx.x;
    if (i >= e) return;
    int s = src[i], d = dst[i];
    float ex = __expf(lrelu(g_el2[s] + g_er2[d]));
    g_exw2[g_pos[i]] = make_int2(s, __float_as_int(ex));
}

// -------- layer-2 agg: two nodes per warp, NO shfl, NO exp --------
__global__ void agg2_kernel(const float* __restrict__ b2,
                            float* __restrict__ out, int n) {
    int warp = (blockIdx.x * blockDim.x + threadIdx.x) >> 5;
    int lane = threadIdx.x & 31;
    int half = lane >> 4;
    int l = lane & 15;
    int node = warp * 2 + half;
    if (node >= n) return;
    int beg = g_rowptr[node], end = g_rowptr[node + 1];

    float acc = 0.f, ssum = 0.f;
#pragma unroll 8
    for (int k = beg; k < end; k++) {
        int2 p = __ldg(&g_exw2[k]);   // uniform within half
        float ex = __int_as_float(p.y);
        ssum += ex;
        acc += ex * __half2float(g_ft2h[p.x * 16 + l]);
    }
    float inv = (ssum > 0.f) ? 1.f / ssum : 0.f;
    out[node * 16 + l] = acc * inv + b2[l] + g_res[node * 16 + l];
    if (l == 0) g_inv2[node] = inv;
}

// ---- edge-parallel alpha output: coalesced read+write in original order ----
__global__ void alpha_kernel(const int* __restrict__ src,
                             const int* __restrict__ dst,
                             float* __restrict__ out_alpha, int e) {
    int i = blockIdx.x * blockDim.x + threadIdx.x;
    if (i >= e) return;
    int s = src[i], d = dst[i];
    float ex = __expf(lrelu(g_el2[s] + g_er2[d]));
    out_alpha[i] = ex * g_inv2[d];
}

// ---------------- launcher ----------------
extern "C" void kernel_launch(void* const* d_in, const int* in_sizes, int n_in,
                              void* d_out, int out_size) {
    const float* h    = (const float*)d_in[0];
    const int*   src  = (const int*)  d_in[1];
    const int*   dst  = (const int*)  d_in[2];
    const float* W1   = (const float*)d_in[3];
    const float* al1  = (const float*)d_in[4];
    const float* ar1  = (const float*)d_in[5];
    const float* b1   = (const float*)d_in[6];
    const float* W2   = (const float*)d_in[7];
    const float* al2  = (const float*)d_in[8];
    const float* ar2  = (const float*)d_in[9];
    const float* b2   = (const float*)d_in[10];
    const float* Wres = (const float*)d_in[11];
    float* out = (float*)d_out;

    int n = in_sizes[0] / F1;
    int e = in_sizes[1];
    if (n > N_MAX || e > E_MAX) return;

    const int T = 256;
    int write_alpha = (out_size >= n * 16 + e) ? 1 : 0;

    static cudaStream_t s_side = nullptr;
    static cudaEvent_t ev_fork = nullptr, ev_join = nullptr;
    if (s_side == nullptr) {
        cudaStreamCreateWithFlags(&s_side, cudaStreamNonBlocking);
        cudaEventCreateWithFlags(&ev_fork, cudaEventDisableTiming);
        cudaEventCreateWithFlags(&ev_join, cudaEventDisableTiming);
    }

    // fork: pack + gemm1 on side stream (independent of CSR build)
    cudaEventRecord(ev_fork, 0);
    cudaStreamWaitEvent(s_side, ev_fork, 0);
    pack_kernel<<<(F1 * F1 + T - 1) / T, T, 0, s_side>>>(W1, W2, Wres);
    gemm1_wmma<<<(n + 31) / 32, 256, 0, s_side>>>(h, al1, ar1, n);
    cudaEventRecord(ev_join, s_side);

    // main chain: CSR build
    int nb = (n + SCAN_B - 1) / SCAN_B;
    deg_kernel<<<(e + 4 * T - 1) / (4 * T), T>>>(dst, e);
    scan_local<<<nb, SCAN_B>>>(n);
    scan_add<<<(n + 1 + T - 1) / T, T>>>(n, e, nb);
    scatter_kernel<<<(e + 2 * T - 1) / (2 * T), T>>>(dst, e);

    // join, then dependent chain
    cudaStreamWaitEvent(0, ev_join, 0);
    exw1_kernel<<<(e + T - 1) / T, T>>>(src, dst, e);
    l2_fused_kernel<<<(n + 15) / 16, 128>>>(b1, al2, ar2, n);
    exw2_kernel<<<(e + T - 1) / T, T>>>(src, dst, e);
    agg2_kernel<<<((long long)((n + 1) / 2) * 32 + T - 1) / T, T>>>(b2, out, n);
    if (write_alpha) {
        alpha_kernel<<<(e + T - 1) / T, T>>>(src, dst, out + n * 16, e);
    }
}

// round 17
// speedup vs baseline: 1.0845x; 1.0845x over previous
#include <cuda_runtime.h>
#include <cuda_fp16.h>
#include <math_constants.h>
#include <mma.h>

using namespace nvcuda;

#define N_MAX 50000
#define E_MAX 800000
#define F1 128
#define SLOPE 0.2f
#define FULL 0xffffffffu
#define SCAN_B 512

// ---------------- scratch ----------------
__device__ __half2 g_ft1h[N_MAX * 64];   // layer-1 features, fp16 pairs
__device__ float2 g_el1[N_MAX];
__device__ float2 g_er1[N_MAX];
__device__ __half g_ft2h[N_MAX * 16];    // layer-2 features (gathered), fp16
__device__ float g_res[N_MAX * 16];      // residual
__device__ float g_el2[N_MAX];
__device__ float g_er2[N_MAX];
__device__ float g_inv2[N_MAX];          // 1/sum for layer-2 softmax
__device__ float g_Wc[F1 * 32];          // [W2 | Wres]
__device__ __half g_W1h[F1 * F1];        // W1 in fp16 (k-major [k][n])
__device__ int g_deg[N_MAX];             // zeroed at load; re-zeroed by scan_add
__device__ int g_rowptr[N_MAX + 1];
__device__ int g_cursor[N_MAX];
__device__ int g_blocksum[128];
__device__ int2 g_edge[E_MAX];           // (src, orig_edge_idx) sorted by dst

__device__ __forceinline__ float lrelu(float x) { return x > 0.f ? x : SLOPE * x; }
__device__ __forceinline__ float eluf(float x)  { return x > 0.f ? x : __expf(x) - 1.f; }

// ---------------- side-stream pack: Wc + W1->fp16 ----------------
__global__ void pack_kernel(const float* __restrict__ W1,
                            const float* __restrict__ W2,
                            const float* __restrict__ Wres) {
    int i = blockIdx.x * blockDim.x + threadIdx.x;
    if (i < F1 * F1) g_W1h[i] = __float2half(W1[i]);
    if (i < F1 * 32) {
        int k = i >> 5, c = i & 31;
        g_Wc[i] = (c < 16) ? W2[k * 16 + c] : Wres[k * 16 + (c - 16)];
    }
}

// ---------------- CSR build ----------------
__global__ void deg_kernel(const int* __restrict__ dst, int e) {
    int base = (blockIdx.x * blockDim.x + threadIdx.x) * 4;
    if (base + 4 <= e) {
        int4 a = *(const int4*)(dst + base);
        atomicAdd(&g_deg[a.x], 1); atomicAdd(&g_deg[a.y], 1);
        atomicAdd(&g_deg[a.z], 1); atomicAdd(&g_deg[a.w], 1);
    } else {
        for (int k = base; k < e; k++) atomicAdd(&g_deg[dst[k]], 1);
    }
}

__global__ void scan_local(int n) {
    __shared__ int sm[SCAN_B];
    int t = threadIdx.x;
    int i = blockIdx.x * SCAN_B + t;
    int v = (i < n) ? g_deg[i] : 0;
    sm[t] = v;
    __syncthreads();
    for (int off = 1; off < SCAN_B; off <<= 1) {
        int u = (t >= off) ? sm[t - off] : 0;
        __syncthreads();
        sm[t] += u;
        __syncthreads();
    }
    if (i < n) g_rowptr[i] = sm[t] - v;
    if (t == SCAN_B - 1) g_blocksum[blockIdx.x] = sm[t];
}

__global__ void scan_add(int n, int e, int nb) {
    __shared__ int bs[128];
    int t = threadIdx.x;
    if (t < 128) bs[t] = (t < nb) ? g_blocksum[t] : 0;
    __syncthreads();
    for (int off = 1; off < 128; off <<= 1) {
        int u = 0;
        if (t < 128 && t >= off) u = bs[t - off];
        __syncthreads();
        if (t < 128) bs[t] += u;
        __syncthreads();
    }
    int i = blockIdx.x * blockDim.x + t;
    if (i < n) {
        int b = i / SCAN_B;
        int v = g_rowptr[i] + ((b == 0) ? 0 : bs[b - 1]);
        g_rowptr[i] = v;
        g_cursor[i] = v;
        g_deg[i] = 0;
    }
    if (i == n) g_rowptr[n] = e;
}

__global__ void scatter_kernel(const int* __restrict__ src,
                               const int* __restrict__ dst, int e) {
    int base = (blockIdx.x * blockDim.x + threadIdx.x) * 2;
    if (base + 2 <= e) {
        int2 d = *(const int2*)(dst + base);
        int2 s = *(const int2*)(src + base);
        int p0 = atomicAdd(&g_cursor[d.x], 1);
        int p1 = atomicAdd(&g_cursor[d.y], 1);
        g_edge[p0] = make_int2(s.x, base);
        g_edge[p1] = make_int2(s.y, base + 1);
    } else {
        for (int k = base; k < e; k++) {
            int pos = atomicAdd(&g_cursor[dst[k]], 1);
            g_edge[pos] = make_int2(src[k], k);
        }
    }
}

// ---------------- GEMM1 via WMMA fp16 + fused el1/er1 ----------------
__global__ void gemm1_wmma(const float* __restrict__ h,
                           const float* __restrict__ al1,
                           const float* __restrict__ ar1, int n) {
    __shared__ __half a_sm[32][F1];
    __shared__ float c_sm[32][F1];
    int t = threadIdx.x;
    int warp = t >> 5, lane = t & 31;
    int row0 = blockIdx.x * 32;

    for (int i = t; i < 1024; i += 256) {
        int r = i >> 5, j4 = i & 31;
        int row = row0 + r;
        float4 v = make_float4(0.f, 0.f, 0.f, 0.f);
        if (row < n) v = *(const float4*)(h + row * F1 + j4 * 4);
        *(__half2*)&a_sm[r][j4 * 4]     = __floats2half2_rn(v.x, v.y);
        *(__half2*)&a_sm[r][j4 * 4 + 2] = __floats2half2_rn(v.z, v.w);
    }
    __syncthreads();

    wmma::fragment<wmma::accumulator, 16, 16, 16, float> c0, c1;
    wmma::fill_fragment(c0, 0.f);
    wmma::fill_fragment(c1, 0.f);
    int trow = (warp >> 2) * 16;
    int tcol = (warp & 3) * 32;
#pragma unroll
    for (int k = 0; k < F1; k += 16) {
        wmma::fragment<wmma::matrix_a, 16, 16, 16, __half, wmma::row_major> a;
        wmma::load_matrix_sync(a, &a_sm[trow][k], F1);
        wmma::fragment<wmma::matrix_b, 16, 16, 16, __half, wmma::row_major> b;
        wmma::load_matrix_sync(b, &g_W1h[k * F1 + tcol], F1);
        wmma::mma_sync(c0, a, b, c0);
        wmma::load_matrix_sync(b, &g_W1h[k * F1 + tcol + 16], F1);
        wmma::mma_sync(c1, a, b, c1);
    }
    wmma::store_matrix_sync(&c_sm[trow][tcol], c0, F1, wmma::mem_row_major);
    wmma::store_matrix_sync(&c_sm[trow][tcol + 16], c1, F1, wmma::mem_row_major);
    __syncthreads();

    for (int i = t; i < 32 * 64; i += 256) {
        int r = i >> 6, c2 = i & 63;
        int row = row0 + r;
        if (row < n)
            g_ft1h[row * 64 + c2] = __floats2half2_rn(c_sm[r][c2 * 2], c_sm[r][c2 * 2 + 1]);
    }
    float a0 = al1[lane], a1 = al1[lane + 32], a2 = al1[lane + 64], a3 = al1[lane + 96];
    float r0 = ar1[lane], r1 = ar1[lane + 32], r2 = ar1[lane + 64], r3 = ar1[lane + 96];
#pragma unroll
    for (int rr = 0; rr < 4; rr++) {
        int r = warp * 4 + rr;
        int row = row0 + r;
        float f0 = c_sm[r][lane], f1 = c_sm[r][lane + 32];
        float f2 = c_sm[r][lane + 64], f3 = c_sm[r][lane + 96];
        float el0 = f0 * a0 + f1 * a1, er0 = f0 * r0 + f1 * r1;
        float el1v = f2 * a2 + f3 * a3, er1v = f2 * r2 + f3 * r3;
#pragma unroll
        for (int o = 16; o; o >>= 1) {
            el0  += __shfl_xor_sync(FULL, el0, o);
            er0  += __shfl_xor_sync(FULL, er0, o);
            el1v += __shfl_xor_sync(FULL, el1v, o);
            er1v += __shfl_xor_sync(FULL, er1v, o);
        }
        if (lane == 0 && row < n) {
            g_el1[row] = make_float2(el0, el1v);
            g_er1[row] = make_float2(er0, er1v);
        }
    }
}

// ------ FUSED: layer-1 agg + GEMM2 + el2/er2 (1 shfl/edge + chunk prefetch) --
__global__ void l2_fused_kernel(const float* __restrict__ b1,
                                const float* __restrict__ al2,
                                const float* __restrict__ ar2, int n) {
    __shared__ float hs[16][F1];
    int t = threadIdx.x;
    int lane = t & 31, w = t >> 5;
    int halfid = lane >> 4, l16 = lane & 15;
    int row0 = blockIdx.x * 16;

    float4 bv = *(const float4*)(b1 + lane * 4);

    // ---- phase A: aggregate 4 nodes per warp ----
#pragma unroll
    for (int rr = 0; rr < 4; rr++) {
        int r = w * 4 + rr;
        int node = row0 + r;
        if (node >= n) {
            *(float4*)&hs[r][lane * 4] = make_float4(0.f, 0.f, 0.f, 0.f);
            continue;
        }
        int beg = g_rowptr[node], end = g_rowptr[node + 1];
        float2 er = g_er1[node];
        float erh = halfid ? er.y : er.x;
        float4 acc = make_float4(0.f, 0.f, 0.f, 0.f);
        float ssum = 0.f;
        // prefetch first chunk's edge + el
        int k0 = beg + l16;
        bool vld = (k0 < end);
        int sidx = 0;
        float elh = 0.f;
        if (vld) {
            sidx = g_edge[k0].x;
            float2 el = g_el1[sidx];
            elh = halfid ? el.y : el.x;
        }
        for (int base = beg; base < end; base += 16) {
            unsigned pk = 0;
            if (vld) {
                float ex = __expf(lrelu(elh + erh));
                ssum += ex;
                pk = (unsigned)sidx |
                     ((unsigned)__half_as_ushort(__float2half_rn(ex)) << 16);
            }
            // prefetch next chunk BEFORE the gather loop (hides el latency)
            int kn = base + 16 + l16;
            vld = (kn < end);
            if (vld) {
                sidx = g_edge[kn].x;
                float2 el = g_el1[sidx];
                elh = halfid ? el.y : el.x;
            }
            int cnt = min(16, end - base);
#pragma unroll 8
            for (int j = 0; j < cnt; j++) {
                unsigned p = __shfl_sync(FULL, pk, j, 16);
                int sj = (int)(p & 0xFFFFu);
                float x = __half2float(__ushort_as_half((unsigned short)(p >> 16)));
                uint2 raw = *(const uint2*)(g_ft1h + sj * 64 + lane * 2);
                float2 f01 = __half22float2(*reinterpret_cast<__half2*>(&raw.x));
                float2 f23 = __half22float2(*reinterpret_cast<__half2*>(&raw.y));
                acc.x += x * f01.x;
                acc.y += x * f01.y;
                acc.z += x * f23.x;
                acc.w += x * f23.y;
            }
        }
#pragma unroll
        for (int o = 8; o; o >>= 1) ssum += __shfl_xor_sync(FULL, ssum, o, 16);
        float inv = (ssum > 0.f) ? 1.f / ssum : 0.f;
        float4 o4;
        o4.x = eluf(acc.x * inv + bv.x);
        o4.y = eluf(acc.y * inv + bv.y);
        o4.z = eluf(acc.z * inv + bv.z);
        o4.w = eluf(acc.w * inv + bv.w);
        *(float4*)&hs[r][lane * 4] = o4;
    }
    __syncthreads();

    // ---- phase B: gemm2 ([ft2 | res] = h1 @ [W2 | Wres]) + eler2 ----
    int c = t & 31, g = t >> 5;
    float acc2[4] = {0.f, 0.f, 0.f, 0.f};
    for (int k = 0; k < F1; k += 4) {
        float w0 = g_Wc[k * 32 + c];
        float w1 = g_Wc[(k + 1) * 32 + c];
        float w2 = g_Wc[(k + 2) * 32 + c];
        float w3 = g_Wc[(k + 3) * 32 + c];
#pragma unroll
        for (int rr = 0; rr < 4; rr++) {
            float4 hv = *(const float4*)&hs[g * 4 + rr][k];
            acc2[rr] += hv.x * w0 + hv.y * w1 + hv.z * w2 + hv.w * w3;
        }
    }
    float a2 = (c < 16) ? al2[c] : 0.f;
    float r2v = (c < 16) ? ar2[c] : 0.f;
#pragma unroll
    for (int rr = 0; rr < 4; rr++) {
        int row = row0 + g * 4 + rr;
        if (row < n) {
            if (c < 16) g_ft2h[row * 16 + c] = __float2half(acc2[rr]);
            else        g_res[row * 16 + (c - 16)] = acc2[rr];
        }
        float el = acc2[rr] * a2, er = acc2[rr] * r2v;
#pragma unroll
        for (int o = 8; o; o >>= 1) {
            el += __shfl_xor_sync(FULL, el, o);
            er += __shfl_xor_sync(FULL, er, o);
        }
        if (c == 0 && row < n) {
            g_el2[row] = el;
            g_er2[row] = er;
        }
    }
}

// -------- layer-2 agg: two nodes/warp, 1 shfl/edge, chunk prefetch --------
__global__ void agg2_kernel(const float* __restrict__ b2,
                            float* __restrict__ out, int n) {
    int warp = (blockIdx.x * blockDim.x + threadIdx.x) >> 5;
    int lane = threadIdx.x & 31;
    int half = lane >> 4;
    int l = lane & 15;
    int node = warp * 2 + half;
    if (node >= n) return;
    unsigned mask = 0xFFFFu << (half * 16);
    int beg = g_rowptr[node], end = g_rowptr[node + 1];
    float er = g_er2[node];

    float acc = 0.f, ssum = 0.f;
    int k0 = beg + l;
    bool vld = (k0 < end);
    int sidx = 0;
    float elv = 0.f;
    if (vld) {
        sidx = g_edge[k0].x;
        elv = g_el2[sidx];
    }
    for (int base = beg; base < end; base += 16) {
        unsigned pk = 0;
        if (vld) {
            float ex = __expf(lrelu(elv + er));
            ssum += ex;
            pk = (unsigned)sidx |
                 ((unsigned)__half_as_ushort(__float2half_rn(ex)) << 16);
        }
        int kn = base + 16 + l;
        vld = (kn < end);
        if (vld) {
            sidx = g_edge[kn].x;
            elv = g_el2[sidx];
        }
        int cnt = min(16, end - base);
#pragma unroll 8
        for (int j = 0; j < cnt; j++) {
            unsigned p = __shfl_sync(mask, pk, j, 16);
            int sj = (int)(p & 0xFFFFu);
            float x = __half2float(__ushort_as_half((unsigned short)(p >> 16)));
            acc += x * __half2float(g_ft2h[sj * 16 + l]);
        }
    }
#pragma unroll
    for (int o = 8; o; o >>= 1) ssum += __shfl_xor_sync(mask, ssum, o);
    float inv = (ssum > 0.f) ? 1.f / ssum : 0.f;
    out[node * 16 + l] = acc * inv + b2[l] + g_res[node * 16 + l];
    if (l == 0) g_inv2[node] = inv;
}

// ---- edge-parallel alpha output: coalesced read+write in original order ----
__global__ void alpha_kernel(const int* __restrict__ src,
                             const int* __restrict__ dst,
                             float* __restrict__ out_alpha, int e) {
    int i = blockIdx.x * blockDim.x + threadIdx.x;
    if (i >= e) return;
    int s = src[i], d = dst[i];
    float ex = __expf(lrelu(g_el2[s] + g_er2[d]));
    out_alpha[i] = ex * g_inv2[d];
}

// ---------------- launcher ----------------
extern "C" void kernel_launch(void* const* d_in, const int* in_sizes, int n_in,
                              void* d_out, int out_size) {
    const float* h    = (const float*)d_in[0];
    const int*   src  = (const int*)  d_in[1];
    const int*   dst  = (const int*)  d_in[2];
    const float* W1   = (const float*)d_in[3];
    const float* al1  = (const float*)d_in[4];
    const float* ar1  = (const float*)d_in[5];
    const float* b1   = (const float*)d_in[6];
    const float* W2   = (const float*)d_in[7];
    const float* al2  = (const float*)d_in[8];
    const float* ar2  = (const float*)d_in[9];
    const float* b2   = (const float*)d_in[10];
    const float* Wres = (const float*)d_in[11];
    float* out = (float*)d_out;

    int n = in_sizes[0] / F1;
    int e = in_sizes[1];
    if (n > N_MAX || e > E_MAX) return;

    const int T = 256;
    int write_alpha = (out_size >= n * 16 + e) ? 1 : 0;

    static cudaStream_t s_side = nullptr;
    static cudaEvent_t ev_fork = nullptr, ev_join = nullptr;
    if (s_side == nullptr) {
        cudaStreamCreateWithFlags(&s_side, cudaStreamNonBlocking);
        cudaEventCreateWithFlags(&ev_fork, cudaEventDisableTiming);
        cudaEventCreateWithFlags(&ev_join, cudaEventDisableTiming);
    }

    // fork: pack + gemm1 on side stream (independent of CSR build)
    cudaEventRecord(ev_fork, 0);
    cudaStreamWaitEvent(s_side, ev_fork, 0);
    pack_kernel<<<(F1 * F1 + T - 1) / T, T, 0, s_side>>>(W1, W2, Wres);
    gemm1_wmma<<<(n + 31) / 32, 256, 0, s_side>>>(h, al1, ar1, n);
    cudaEventRecord(ev_join, s_side);

    // main chain: CSR build
    int nb = (n + SCAN_B - 1) / SCAN_B;
    deg_kernel<<<(e + 4 * T - 1) / (4 * T), T>>>(dst, e);
    scan_local<<<nb, SCAN_B>>>(n);
    scan_add<<<(n + 1 + T - 1) / T, T>>>(n, e, nb);
    scatter_kernel<<<(e + 2 * T - 1) / (2 * T), T>>>(src, dst, e);

    // join, then dependent chain
    cudaStreamWaitEvent(0, ev_join, 0);
    l2_fused_kernel<<<(n + 15) / 16, 128>>>(b1, al2, ar2, n);
    agg2_kernel<<<((long long)((n + 1) / 2) * 32 + T - 1) / T, T>>>(b2, out, n);
    if (write_alpha) {
        alpha_kernel<<<(e + T - 1) / T, T>>>(src, dst, out + n * 16, e);
    }
}